// round 4
// baseline (speedup 1.0000x reference)
#include <cuda_runtime.h>
#include <math.h>

#define NN 20000
#define FF 8
#define PP 12
#define OO 32
#define EE 320000
#define FP 96          // F*P floats per node row
#define NBLK 148
#define NTHR 512
#define NWARP (NBLK * (NTHR/32))   // 2368 warps total

// ---- scratch (static device globals; no allocation allowed) ----
__device__ int      g_cnt[NN];        // in-degree histogram
__device__ int      g_rowoff[NN + 1]; // CSR row offsets (by dst)
__device__ int      g_cursor[NN];     // scatter cursors
__device__ int      g_col[EE];        // CSR column (src) indices
__device__ float    g_dinv[NN];       // (in_deg + 1)^-1/2
__device__ float    g_cwz[FF * OO];   // fused Wz @ Lz^T
__device__ float    g_cwh[FF * OO];   // fused Wh @ Lh^T
__device__ float    g_cbz[OO];
__device__ float    g_cbh[OO];
__device__ float    g_probs[PP];
__device__ unsigned g_bar[4];         // grid-barrier counters (reset at kernel end)

// Software grid barrier: all NBLK blocks are co-resident (1 block/SM).
__device__ __forceinline__ void grid_barrier(int id) {
    __syncthreads();
    if (threadIdx.x == 0) {
        __threadfence();                                   // release
        unsigned arrived = atomicAdd(&g_bar[id], 1u) + 1u;
        if (arrived < NBLK) {
            while (*(volatile unsigned*)&g_bar[id] < NBLK) { }
        }
        __threadfence();                                   // acquire
    }
    __syncthreads();
}

__global__ void __launch_bounds__(NTHR, 1) fused_kernel(
        const float* __restrict__ x,
        const int*   __restrict__ ei,
        const float* __restrict__ Wz,  const float* __restrict__ bz,
        const float* __restrict__ Wh,  const float* __restrict__ bh,
        const float* __restrict__ lzw, const float* __restrict__ lzb,
        const float* __restrict__ lhw, const float* __restrict__ lhb,
        const float* __restrict__ att,
        const float* __restrict__ out_w, const float* __restrict__ out_b,
        float* __restrict__ out) {
    const int t    = threadIdx.x;
    const int lane = t & 31;
    const int warp = t >> 5;                 // 0..15
    const int gid  = blockIdx.x * NTHR + t;  // 0..75775
    const int T    = NBLK * NTHR;

    __shared__ int   wsum[17];               // scan partials
    __shared__ float buf[NTHR / 32][FP];     // GRU staging, per warp

    // ---------------- P0: zero histogram + fold weights (block 0) ----------
    for (int j = gid; j < NN; j += T) g_cnt[j] = 0;

    if (blockIdx.x == 0) {
        if (t < 256) {                       // W'_z[f][o] = sum_k Wz[f][k]*lzw[o][k]
            int f = t >> 5, o = t & 31;
            float s = 0.f;
            #pragma unroll
            for (int k = 0; k < 32; ++k) s = fmaf(Wz[f * 32 + k], lzw[o * 64 + k], s);
            g_cwz[t] = s;
        } else {                             // W'_h
            int i = t - 256;
            int f = i >> 5, o = i & 31;
            float s = 0.f;
            #pragma unroll
            for (int k = 0; k < 32; ++k) s = fmaf(Wh[f * 32 + k], lhw[o * 64 + k], s);
            g_cwh[i] = s;
        }
        if (t < 32) {                        // b'_z
            float s = lzb[t];
            #pragma unroll
            for (int k = 0; k < 32; ++k) s = fmaf(bz[k], lzw[t * 64 + k], s);
            g_cbz[t] = s;
        } else if (t < 64) {                 // b'_h
            int o = t - 32;
            float s = lhb[o];
            #pragma unroll
            for (int k = 0; k < 32; ++k) s = fmaf(bh[k], lhw[o * 64 + k], s);
            g_cbh[o] = s;
        }
        if (t == 0) {                        // softmax over 12 logits
            float m = att[0];
            for (int p = 1; p < PP; ++p) m = fmaxf(m, att[p]);
            float e[PP], sum = 0.f;
            for (int p = 0; p < PP; ++p) { e[p] = __expf(att[p] - m); sum += e[p]; }
            float inv = 1.f / sum;
            for (int p = 0; p < PP; ++p) g_probs[p] = e[p] * inv;
        }
    }
    grid_barrier(0);

    // ---------------- P1: in-degree histogram (int4, ILP=4) ----------------
    {
        const int4* d4p = (const int4*)(ei + EE);
        for (int q = gid; q < EE / 4; q += T) {
            int4 d4 = d4p[q];
            atomicAdd(&g_cnt[d4.x], 1);
            atomicAdd(&g_cnt[d4.y], 1);
            atomicAdd(&g_cnt[d4.z], 1);
            atomicAdd(&g_cnt[d4.w], 1);
        }
    }
    grid_barrier(1);

    // ---------------- P2: scan (block 0 only, coalesced tiles) -------------
    if (blockIdx.x == 0) {
        int running = 0;
        const int NTILE = (NN + NTHR - 1) / NTHR;   // 40
        for (int tile = 0; tile < NTILE; ++tile) {
            int idx = tile * NTHR + t;
            int v = (idx < NN) ? __ldcg(&g_cnt[idx]) : 0;
            int inc = v;                              // inclusive warp scan
            #pragma unroll
            for (int off = 1; off < 32; off <<= 1) {
                int u = __shfl_up_sync(0xffffffffu, inc, off);
                if (lane >= off) inc += u;
            }
            if (lane == 31) wsum[warp] = inc;
            __syncthreads();
            if (warp == 0 && lane < 16) {             // scan 16 warp totals
                int w = wsum[lane];
                int wi = w;
                #pragma unroll
                for (int off = 1; off < 16; off <<= 1) {
                    int u = __shfl_up_sync(0x0000ffffu, wi, off);
                    if (lane >= off) wi += u;
                }
                wsum[lane] = wi - w;                  // exclusive
                if (lane == 15) wsum[16] = wi;        // tile total
            }
            __syncthreads();
            int excl = running + wsum[warp] + inc - v;
            if (idx < NN) {
                g_rowoff[idx] = excl;
                g_cursor[idx] = excl;
                g_dinv[idx]   = rsqrtf((float)(v + 1));   // +1 self-loop
            }
            running += wsum[16];
            __syncthreads();
        }
        if (t == 0) g_rowoff[NN] = EE;
    }
    grid_barrier(2);

    // ---------------- P3: scatter src into dst-sorted CSR ------------------
    {
        const int4* s4p = (const int4*)ei;
        const int4* d4p = (const int4*)(ei + EE);
        for (int q = gid; q < EE / 4; q += T) {
            int4 s4 = s4p[q];
            int4 d4 = d4p[q];
            int p0 = atomicAdd(&g_cursor[d4.x], 1);
            int p1 = atomicAdd(&g_cursor[d4.y], 1);
            int p2 = atomicAdd(&g_cursor[d4.z], 1);
            int p3 = atomicAdd(&g_cursor[d4.w], 1);
            g_col[p0] = s4.x;
            g_col[p1] = s4.y;
            g_col[p2] = s4.z;
            g_col[p3] = s4.w;
        }
    }
    grid_barrier(3);

    // reset barrier counters for the next graph replay (everyone is past all
    // barriers now; next launch starts only after this kernel completes)
    if (blockIdx.x == 0 && t < 4) g_bar[t] = 0;

    // ---------------- P4: gather + GRU + attention + readout ---------------
    {
        // per-warp constants (hoisted out of the node loop)
        float wz[FF], wh[FF];
        #pragma unroll
        for (int f = 0; f < FF; ++f) {
            wz[f] = g_cwz[f * OO + lane];
            wh[f] = g_cwh[f * OO + lane];
        }
        const float bz_ = g_cbz[lane];
        const float bh_ = g_cbh[lane];
        float probs[PP];
        #pragma unroll
        for (int p = 0; p < PP; ++p) probs[p] = g_probs[p];

        const int gwarp = blockIdx.x * (NTHR / 32) + warp;
        for (int node = gwarp; node < NN; node += NWARP) {
            int beg = g_rowoff[node];
            int end = g_rowoff[node + 1];
            float di = g_dinv[node];

            float a0 = 0.f, a1 = 0.f, a2 = 0.f;
            int j = beg;
            for (; j + 4 <= end; j += 4) {
                int s0 = g_col[j], s1 = g_col[j+1], s2 = g_col[j+2], s3 = g_col[j+3];
                float w0 = g_dinv[s0], w1 = g_dinv[s1], w2 = g_dinv[s2], w3 = g_dinv[s3];
                const float* x0 = x + (size_t)s0 * FP;
                const float* x1 = x + (size_t)s1 * FP;
                const float* x2 = x + (size_t)s2 * FP;
                const float* x3 = x + (size_t)s3 * FP;
                float v00 = x0[lane], v01 = x0[lane+32], v02 = x0[lane+64];
                float v10 = x1[lane], v11 = x1[lane+32], v12 = x1[lane+64];
                float v20 = x2[lane], v21 = x2[lane+32], v22 = x2[lane+64];
                float v30 = x3[lane], v31 = x3[lane+32], v32 = x3[lane+64];
                a0 = fmaf(w0, v00, a0); a1 = fmaf(w0, v01, a1); a2 = fmaf(w0, v02, a2);
                a0 = fmaf(w1, v10, a0); a1 = fmaf(w1, v11, a1); a2 = fmaf(w1, v12, a2);
                a0 = fmaf(w2, v20, a0); a1 = fmaf(w2, v21, a1); a2 = fmaf(w2, v22, a2);
                a0 = fmaf(w3, v30, a0); a1 = fmaf(w3, v31, a1); a2 = fmaf(w3, v32, a2);
            }
            for (; j < end; ++j) {
                int s0 = g_col[j];
                float w0 = g_dinv[s0];
                const float* x0 = x + (size_t)s0 * FP;
                a0 = fmaf(w0, x0[lane],      a0);
                a1 = fmaf(w0, x0[lane + 32], a1);
                a2 = fmaf(w0, x0[lane + 64], a2);
            }
            // agg = di * (acc + di * x_self)
            const float* xs = x + (size_t)node * FP;
            a0 = di * fmaf(di, xs[lane],      a0);
            a1 = di * fmaf(di, xs[lane + 32], a1);
            a2 = di * fmaf(di, xs[lane + 64], a2);

            __syncwarp();                    // prev iteration's buf reads done
            buf[warp][lane]      = a0;
            buf[warp][lane + 32] = a1;
            buf[warp][lane + 64] = a2;
            __syncwarp();

            float hacc = 0.f;
            #pragma unroll
            for (int p = 0; p < PP; ++p) {
                float z = bz_, h = bh_;
                #pragma unroll
                for (int f = 0; f < FF; ++f) {
                    float v = buf[warp][f * PP + p];   // broadcast LDS
                    z = fmaf(v, wz[f], z);
                    h = fmaf(v, wh[f], h);
                }
                float Z = 1.f / (1.f + __expf(-z));              // sigmoid
                float Th = 2.f / (1.f + __expf(-2.f * h)) - 1.f; // tanh
                hacc = fmaf(probs[p], (1.f - Z) * Th, hacc);     // (1-Z)*Ht (H==0)
            }
            float hr = fmaxf(hacc, 0.f);     // relu

            #pragma unroll
            for (int p = 0; p < PP; ++p) {
                float v = hr * __ldg(&out_w[p * OO + lane]);
                v += __shfl_xor_sync(0xffffffffu, v, 16);
                v += __shfl_xor_sync(0xffffffffu, v, 8);
                v += __shfl_xor_sync(0xffffffffu, v, 4);
                v += __shfl_xor_sync(0xffffffffu, v, 2);
                v += __shfl_xor_sync(0xffffffffu, v, 1);
                if (lane == 0) out[node * PP + p] = v + __ldg(&out_b[p]);
            }
        }
    }
}

// ---------------------------------------------------------------------------
extern "C" void kernel_launch(void* const* d_in, const int* in_sizes, int n_in,
                              void* d_out, int out_size) {
    const float* x    = (const float*)d_in[0];
    const int*   ei   = (const int*)  d_in[1];
    const float* Wz   = (const float*)d_in[2];
    const float* bz   = (const float*)d_in[3];
    // d_in[4], d_in[5]: Wr, br — dead code (H == 0 kills the reset gate)
    const float* Wh   = (const float*)d_in[6];
    const float* bh   = (const float*)d_in[7];
    const float* lzw  = (const float*)d_in[8];
    const float* lzb  = (const float*)d_in[9];
    // d_in[10], d_in[11]: lr_w, lr_b — unused
    const float* lhw  = (const float*)d_in[12];
    const float* lhb  = (const float*)d_in[13];
    const float* att  = (const float*)d_in[14];
    const float* outw = (const float*)d_in[15];
    const float* outb = (const float*)d_in[16];
    float* out = (float*)d_out;

    fused_kernel<<<NBLK, NTHR>>>(x, ei, Wz, bz, Wh, bh, lzw, lzb, lhw, lhb,
                                 att, outw, outb, out);
}

// round 5
// speedup vs baseline: 1.6670x; 1.6670x over previous
#include <cuda_runtime.h>
#include <math.h>

#define NN 20000
#define FF 8
#define PP 12
#define OO 32
#define EE 320000
#define FP 96           // F*P floats per node row
#define SLOTS 96        // max in-degree slots (Poisson(16): P(>=96) ~ 1e-44; guarded)
#define NBLK 296
#define NTHR 512
#define NWARP (NBLK * (NTHR / 32))   // 4736 warps

// ---- scratch (static device globals; no allocation allowed) ----
__device__ int      g_cnt[NN];            // in-degree (atomic counters)
__device__ int      g_col[NN * SLOTS];    // slotted adjacency: srcs per dst
__device__ float    g_dinv[NN];           // (in_deg + 1)^-1/2
__device__ float    g_cwz[FF * OO];       // fused Wz @ Lz^T
__device__ float    g_cwh[FF * OO];       // fused Wh @ Lh^T
__device__ float    g_cbz[OO];
__device__ float    g_cbh[OO];
__device__ float    g_probs[PP];
__device__ unsigned g_bar[3];             // monotonic barrier counters (never reset)

// Monotonic grid barrier: co-resident blocks (2/SM guaranteed by launch bounds).
// Counter never resets -> safe across CUDA-graph replays (no reset race).
__device__ __forceinline__ void grid_barrier(int id) {
    __syncthreads();
    if (threadIdx.x == 0) {
        __threadfence();                                      // release
        unsigned arrived = atomicAdd(&g_bar[id], 1u) + 1u;
        unsigned target  = ((arrived + NBLK - 1u) / NBLK) * NBLK;
        while (*(volatile unsigned*)&g_bar[id] < target) { }
        __threadfence();                                      // acquire
    }
    __syncthreads();
}

__global__ void __launch_bounds__(NTHR, 2) fused_kernel(
        const float* __restrict__ x,
        const int*   __restrict__ ei,
        const float* __restrict__ Wz,  const float* __restrict__ bz,
        const float* __restrict__ Wh,  const float* __restrict__ bh,
        const float* __restrict__ lzw, const float* __restrict__ lzb,
        const float* __restrict__ lhw, const float* __restrict__ lhb,
        const float* __restrict__ att,
        const float* __restrict__ out_w, const float* __restrict__ out_b,
        float* __restrict__ out) {
    const int t    = threadIdx.x;
    const int lane = t & 31;
    const int warp = t >> 5;                 // 0..15
    const int gid  = blockIdx.x * NTHR + t;
    const int T    = NBLK * NTHR;

    __shared__ float buf[NTHR / 32][FP];     // GRU staging, per warp

    // ---------------- P0: zero counters + fold weights (block 0) -----------
    for (int j = gid; j < NN; j += T) g_cnt[j] = 0;

    if (blockIdx.x == 0) {
        if (t < 256) {                       // W'_z[f][o] = sum_k Wz[f][k]*lzw[o][k]
            int f = t >> 5, o = t & 31;
            float s = 0.f;
            #pragma unroll
            for (int k = 0; k < 32; ++k) s = fmaf(Wz[f * 32 + k], lzw[o * 64 + k], s);
            g_cwz[t] = s;
        } else {                             // W'_h
            int i = t - 256;
            int f = i >> 5, o = i & 31;
            float s = 0.f;
            #pragma unroll
            for (int k = 0; k < 32; ++k) s = fmaf(Wh[f * 32 + k], lhw[o * 64 + k], s);
            g_cwh[i] = s;
        }
        if (t < 32) {                        // b'_z
            float s = lzb[t];
            #pragma unroll
            for (int k = 0; k < 32; ++k) s = fmaf(bz[k], lzw[t * 64 + k], s);
            g_cbz[t] = s;
        } else if (t < 64) {                 // b'_h
            int o = t - 32;
            float s = lhb[o];
            #pragma unroll
            for (int k = 0; k < 32; ++k) s = fmaf(bh[k], lhw[o * 64 + k], s);
            g_cbh[o] = s;
        }
        if (t == 0) {                        // softmax over 12 logits
            float m = att[0];
            for (int p = 1; p < PP; ++p) m = fmaxf(m, att[p]);
            float e[PP], sum = 0.f;
            for (int p = 0; p < PP; ++p) { e[p] = __expf(att[p] - m); sum += e[p]; }
            float inv = 1.f / sum;
            for (int p = 0; p < PP; ++p) g_probs[p] = e[p] * inv;
        }
    }
    grid_barrier(0);

    // ---------------- P1: single-pass slotted scatter (counts + adjacency) -
    {
        const int4* s4p = (const int4*)ei;
        const int4* d4p = (const int4*)(ei + EE);
        for (int q = gid; q < EE / 4; q += T) {
            int4 s4 = s4p[q];
            int4 d4 = d4p[q];
            int p0 = atomicAdd(&g_cnt[d4.x], 1);
            int p1 = atomicAdd(&g_cnt[d4.y], 1);
            int p2 = atomicAdd(&g_cnt[d4.z], 1);
            int p3 = atomicAdd(&g_cnt[d4.w], 1);
            if (p0 < SLOTS) g_col[d4.x * SLOTS + p0] = s4.x;
            if (p1 < SLOTS) g_col[d4.y * SLOTS + p1] = s4.y;
            if (p2 < SLOTS) g_col[d4.z * SLOTS + p2] = s4.z;
            if (p3 < SLOTS) g_col[d4.w * SLOTS + p3] = s4.w;
        }
    }
    grid_barrier(1);

    // ---------------- P2: dinv = (deg+1)^-1/2 ------------------------------
    for (int j = gid; j < NN; j += T)
        g_dinv[j] = rsqrtf((float)(__ldcg(&g_cnt[j]) + 1));
    grid_barrier(2);

    // ---------------- P3: gather + GRU + attention + readout ---------------
    {
        float wz[FF], wh[FF];
        #pragma unroll
        for (int f = 0; f < FF; ++f) {
            wz[f] = g_cwz[f * OO + lane];
            wh[f] = g_cwh[f * OO + lane];
        }
        const float bz_ = g_cbz[lane];
        const float bh_ = g_cbh[lane];

        const int gwarp = blockIdx.x * (NTHR / 32) + warp;
        for (int node = gwarp; node < NN; node += NWARP) {
            int deg = g_cnt[node];
            if (deg > SLOTS) deg = SLOTS;
            const int* cols = g_col + node * SLOTS;
            float di = g_dinv[node];

            float a0 = 0.f, a1 = 0.f, a2 = 0.f;
            int j = 0;
            for (; j + 2 <= deg; j += 2) {
                int s0 = __ldg(&cols[j]);
                int s1 = __ldg(&cols[j + 1]);
                float w0 = __ldg(&g_dinv[s0]);
                float w1 = __ldg(&g_dinv[s1]);
                const float* x0 = x + (size_t)s0 * FP;
                const float* x1 = x + (size_t)s1 * FP;
                float v00 = __ldg(x0 + lane), v01 = __ldg(x0 + lane + 32), v02 = __ldg(x0 + lane + 64);
                float v10 = __ldg(x1 + lane), v11 = __ldg(x1 + lane + 32), v12 = __ldg(x1 + lane + 64);
                a0 = fmaf(w0, v00, a0); a1 = fmaf(w0, v01, a1); a2 = fmaf(w0, v02, a2);
                a0 = fmaf(w1, v10, a0); a1 = fmaf(w1, v11, a1); a2 = fmaf(w1, v12, a2);
            }
            if (j < deg) {
                int s0 = __ldg(&cols[j]);
                float w0 = __ldg(&g_dinv[s0]);
                const float* x0 = x + (size_t)s0 * FP;
                a0 = fmaf(w0, __ldg(x0 + lane),      a0);
                a1 = fmaf(w0, __ldg(x0 + lane + 32), a1);
                a2 = fmaf(w0, __ldg(x0 + lane + 64), a2);
            }
            // agg = di * (acc + di * x_self)
            const float* xs = x + (size_t)node * FP;
            a0 = di * fmaf(di, __ldg(xs + lane),      a0);
            a1 = di * fmaf(di, __ldg(xs + lane + 32), a1);
            a2 = di * fmaf(di, __ldg(xs + lane + 64), a2);

            __syncwarp();                    // previous iteration's buf reads done
            buf[warp][lane]      = a0;
            buf[warp][lane + 32] = a1;
            buf[warp][lane + 64] = a2;
            __syncwarp();

            float hacc = 0.f;
            #pragma unroll
            for (int p = 0; p < PP; ++p) {
                float z = bz_, h = bh_;
                #pragma unroll
                for (int f = 0; f < FF; ++f) {
                    float v = buf[warp][f * PP + p];   // broadcast LDS
                    z = fmaf(v, wz[f], z);
                    h = fmaf(v, wh[f], h);
                }
                float Z  = 1.f / (1.f + __expf(-z));              // sigmoid
                float Th = 2.f / (1.f + __expf(-2.f * h)) - 1.f;  // tanh
                hacc = fmaf(g_probs[p], (1.f - Z) * Th, hacc);    // (1-Z)*Ht (H==0)
            }
            float hr = fmaxf(hacc, 0.f);     // relu

            #pragma unroll
            for (int p = 0; p < PP; ++p) {
                float v = hr * __ldg(&out_w[p * OO + lane]);
                v += __shfl_xor_sync(0xffffffffu, v, 16);
                v += __shfl_xor_sync(0xffffffffu, v, 8);
                v += __shfl_xor_sync(0xffffffffu, v, 4);
                v += __shfl_xor_sync(0xffffffffu, v, 2);
                v += __shfl_xor_sync(0xffffffffu, v, 1);
                if (lane == 0) out[node * PP + p] = v + __ldg(&out_b[p]);
            }
        }
    }
}

// ---------------------------------------------------------------------------
extern "C" void kernel_launch(void* const* d_in, const int* in_sizes, int n_in,
                              void* d_out, int out_size) {
    const float* x    = (const float*)d_in[0];
    const int*   ei   = (const int*)  d_in[1];
    const float* Wz   = (const float*)d_in[2];
    const float* bz   = (const float*)d_in[3];
    // d_in[4], d_in[5]: Wr, br — dead code (H == 0 kills the reset gate)
    const float* Wh   = (const float*)d_in[6];
    const float* bh   = (const float*)d_in[7];
    const float* lzw  = (const float*)d_in[8];
    const float* lzb  = (const float*)d_in[9];
    // d_in[10], d_in[11]: lr_w, lr_b — unused
    const float* lhw  = (const float*)d_in[12];
    const float* lhb  = (const float*)d_in[13];
    const float* att  = (const float*)d_in[14];
    const float* outw = (const float*)d_in[15];
    const float* outb = (const float*)d_in[16];
    float* out = (float*)d_out;

    fused_kernel<<<NBLK, NTHR>>>(x, ei, Wz, bz, Wh, bh, lzw, lzb, lhw, lhb,
                                 att, outw, outb, out);
}

// round 6
// speedup vs baseline: 1.7148x; 1.0286x over previous
#include <cuda_runtime.h>
#include <math.h>

#define NN 20000
#define FF 8
#define PP 12
#define OO 32
#define EE 320000
#define FP 96           // F*P floats per node row
#define SLOTS 96        // max in-degree slots (Poisson(16); guarded)
#define NSM 148
#define NBPS 6
#define NBLK (NSM * NBPS)            // 888 blocks, all co-resident
#define NTHR 256
#define WPB (NTHR / 32)              // 8 warps per block
#define NWARP (NBLK * WPB)           // 7104 warps

// ---- scratch (static device globals; no allocation allowed) ----
__device__ int      g_cnt[NN];            // in-degree (atomic counters)
__device__ int      g_col[NN * SLOTS];    // slotted adjacency: srcs per dst
__device__ float    g_dinv[NN];           // (in_deg + 1)^-1/2
__device__ float    g_cwz[FF * OO];       // fused Wz @ Lz^T
__device__ float    g_cwh[FF * OO];       // fused Wh @ Lh^T
__device__ float    g_cbz[OO];
__device__ float    g_cbh[OO];
__device__ float    g_probs[PP];
__device__ unsigned g_bar[3];             // monotonic barrier counters (never reset)

// Monotonic grid barrier: all NBLK blocks co-resident (6/SM via launch bounds).
// Counter never resets -> safe across CUDA-graph replays.
__device__ __forceinline__ void grid_barrier(int id) {
    __syncthreads();
    if (threadIdx.x == 0) {
        __threadfence();                                      // release
        unsigned arrived = atomicAdd(&g_bar[id], 1u) + 1u;
        unsigned target  = ((arrived + NBLK - 1u) / NBLK) * NBLK;
        while (*(volatile unsigned*)&g_bar[id] < target) { }
        __threadfence();                                      // acquire
    }
    __syncthreads();
}

__global__ void __launch_bounds__(NTHR, NBPS) fused_kernel(
        const float* __restrict__ x,
        const int*   __restrict__ ei,
        const float* __restrict__ Wz,  const float* __restrict__ bz,
        const float* __restrict__ Wh,  const float* __restrict__ bh,
        const float* __restrict__ lzw, const float* __restrict__ lzb,
        const float* __restrict__ lhw, const float* __restrict__ lhb,
        const float* __restrict__ att,
        const float* __restrict__ out_w, const float* __restrict__ out_b,
        float* __restrict__ out) {
    const int t    = threadIdx.x;
    const int lane = t & 31;
    const int warp = t >> 5;                 // 0..7
    const int gid  = blockIdx.x * NTHR + t;
    const int T    = NBLK * NTHR;

    __shared__ float buf[WPB][FP];           // GRU staging, per warp
    __shared__ float sow[PP * OO];           // staged out_w
    __shared__ float sob[PP];                // staged out_b
    __shared__ float sprobs[PP];             // staged softmax(att)

    // ---------------- P0: zero counters + fold weights (blocks 0..2) -------
    for (int j = gid; j < NN; j += T) g_cnt[j] = 0;

    if (blockIdx.x == 0) {                   // W'_z[f][o] = sum_k Wz[f][k]*lzw[o][k]
        int f = t >> 5, o = t & 31;
        float s = 0.f;
        #pragma unroll
        for (int k = 0; k < 32; ++k) s = fmaf(Wz[f * 32 + k], lzw[o * 64 + k], s);
        g_cwz[t] = s;
    } else if (blockIdx.x == 1) {            // W'_h
        int f = t >> 5, o = t & 31;
        float s = 0.f;
        #pragma unroll
        for (int k = 0; k < 32; ++k) s = fmaf(Wh[f * 32 + k], lhw[o * 64 + k], s);
        g_cwh[t] = s;
    } else if (blockIdx.x == 2) {
        if (t < 32) {                        // b'_z
            float s = lzb[t];
            #pragma unroll
            for (int k = 0; k < 32; ++k) s = fmaf(bz[k], lzw[t * 64 + k], s);
            g_cbz[t] = s;
        } else if (t < 64) {                 // b'_h
            int o = t - 32;
            float s = lhb[o];
            #pragma unroll
            for (int k = 0; k < 32; ++k) s = fmaf(bh[k], lhw[o * 64 + k], s);
            g_cbh[o] = s;
        } else if (t == 64) {                // softmax over 12 logits
            float m = att[0];
            for (int p = 1; p < PP; ++p) m = fmaxf(m, att[p]);
            float e[PP], sum = 0.f;
            for (int p = 0; p < PP; ++p) { e[p] = __expf(att[p] - m); sum += e[p]; }
            float inv = 1.f / sum;
            for (int p = 0; p < PP; ++p) g_probs[p] = e[p] * inv;
        }
    }
    grid_barrier(0);

    // ---------------- P1: single-pass slotted scatter -----------------------
    {
        const int4* s4p = (const int4*)ei;
        const int4* d4p = (const int4*)(ei + EE);
        for (int q = gid; q < EE / 4; q += T) {
            int4 s4 = s4p[q];
            int4 d4 = d4p[q];
            int p0 = atomicAdd(&g_cnt[d4.x], 1);
            int p1 = atomicAdd(&g_cnt[d4.y], 1);
            int p2 = atomicAdd(&g_cnt[d4.z], 1);
            int p3 = atomicAdd(&g_cnt[d4.w], 1);
            if (p0 < SLOTS) g_col[d4.x * SLOTS + p0] = s4.x;
            if (p1 < SLOTS) g_col[d4.y * SLOTS + p1] = s4.y;
            if (p2 < SLOTS) g_col[d4.z * SLOTS + p2] = s4.z;
            if (p3 < SLOTS) g_col[d4.w * SLOTS + p3] = s4.w;
        }
    }
    grid_barrier(1);

    // ---------------- P2: dinv = (deg+1)^-1/2 ------------------------------
    for (int j = gid; j < NN; j += T)
        g_dinv[j] = rsqrtf((float)(__ldcg(&g_cnt[j]) + 1));
    grid_barrier(2);

    // ---------------- P3: gather + GRU + attention + readout ---------------
    {
        // stage small constants into smem (relieves registers, kills GMEM lat)
        if (t < PP)           sprobs[t] = g_probs[t];
        if (t < PP)           sob[t]    = out_b[t];
        for (int j = t; j < PP * OO; j += NTHR) sow[j] = out_w[j];
        __syncthreads();

        float wz[FF], wh[FF];
        #pragma unroll
        for (int f = 0; f < FF; ++f) {
            wz[f] = g_cwz[f * OO + lane];
            wh[f] = g_cwh[f * OO + lane];
        }
        const float bz_ = g_cbz[lane];
        const float bh_ = g_cbh[lane];

        const int gwarp = blockIdx.x * WPB + warp;
        for (int node = gwarp; node < NN; node += NWARP) {
            int deg = g_cnt[node];
            if (deg > SLOTS) deg = SLOTS;
            const int* cols = g_col + node * SLOTS;
            float di = g_dinv[node];

            // ---- gather: lanes 0..23 each own one float4 of the 96-row ----
            if (lane < 24) {
                float4 acc = make_float4(0.f, 0.f, 0.f, 0.f);
                int j = 0;
                for (; j + 2 <= deg; j += 2) {
                    int2 ss = *(const int2*)&cols[j];         // 8B-aligned
                    float w0 = __ldg(&g_dinv[ss.x]);
                    float w1 = __ldg(&g_dinv[ss.y]);
                    float4 v0 = __ldg((const float4*)(x + (size_t)ss.x * FP) + lane);
                    float4 v1 = __ldg((const float4*)(x + (size_t)ss.y * FP) + lane);
                    acc.x = fmaf(w0, v0.x, acc.x); acc.y = fmaf(w0, v0.y, acc.y);
                    acc.z = fmaf(w0, v0.z, acc.z); acc.w = fmaf(w0, v0.w, acc.w);
                    acc.x = fmaf(w1, v1.x, acc.x); acc.y = fmaf(w1, v1.y, acc.y);
                    acc.z = fmaf(w1, v1.z, acc.z); acc.w = fmaf(w1, v1.w, acc.w);
                }
                if (j < deg) {
                    int s0 = __ldg(&cols[j]);
                    float w0 = __ldg(&g_dinv[s0]);
                    float4 v0 = __ldg((const float4*)(x + (size_t)s0 * FP) + lane);
                    acc.x = fmaf(w0, v0.x, acc.x); acc.y = fmaf(w0, v0.y, acc.y);
                    acc.z = fmaf(w0, v0.z, acc.z); acc.w = fmaf(w0, v0.w, acc.w);
                }
                // agg = di * (acc + di * x_self)
                float4 xv = __ldg((const float4*)(x + (size_t)node * FP) + lane);
                acc.x = di * fmaf(di, xv.x, acc.x);
                acc.y = di * fmaf(di, xv.y, acc.y);
                acc.z = di * fmaf(di, xv.z, acc.z);
                acc.w = di * fmaf(di, xv.w, acc.w);
                ((float4*)buf[warp])[lane] = acc;
            }
            __syncwarp();

            // ---- GRU: two periods per iteration (float2 LDS) --------------
            float hacc = 0.f;
            #pragma unroll
            for (int pp = 0; pp < PP / 2; ++pp) {
                float z0 = bz_, z1 = bz_, h0 = bh_, h1 = bh_;
                #pragma unroll
                for (int f = 0; f < FF; ++f) {
                    float2 v = *(const float2*)&buf[warp][f * PP + 2 * pp];
                    z0 = fmaf(v.x, wz[f], z0); z1 = fmaf(v.y, wz[f], z1);
                    h0 = fmaf(v.x, wh[f], h0); h1 = fmaf(v.y, wh[f], h1);
                }
                float Z0 = 1.f / (1.f + __expf(-z0));
                float Z1 = 1.f / (1.f + __expf(-z1));
                float T0 = 2.f / (1.f + __expf(-2.f * h0)) - 1.f;
                float T1 = 2.f / (1.f + __expf(-2.f * h1)) - 1.f;
                hacc = fmaf(sprobs[2 * pp],     (1.f - Z0) * T0, hacc);
                hacc = fmaf(sprobs[2 * pp + 1], (1.f - Z1) * T1, hacc);
            }
            float hr = fmaxf(hacc, 0.f);     // relu
            __syncwarp();                    // buf reads done before next write

            // ---- readout: 12 warp reductions, result lands on lane p ------
            float myout = 0.f;
            #pragma unroll
            for (int p = 0; p < PP; ++p) {
                float v = hr * sow[p * OO + lane];
                v += __shfl_xor_sync(0xffffffffu, v, 16);
                v += __shfl_xor_sync(0xffffffffu, v, 8);
                v += __shfl_xor_sync(0xffffffffu, v, 4);
                v += __shfl_xor_sync(0xffffffffu, v, 2);
                v += __shfl_xor_sync(0xffffffffu, v, 1);
                if (lane == p) myout = v + sob[p];
            }
            if (lane < PP) out[node * PP + lane] = myout;   // one coalesced STG
        }
    }
}

// ---------------------------------------------------------------------------
extern "C" void kernel_launch(void* const* d_in, const int* in_sizes, int n_in,
                              void* d_out, int out_size) {
    const float* x    = (const float*)d_in[0];
    const int*   ei   = (const int*)  d_in[1];
    const float* Wz   = (const float*)d_in[2];
    const float* bz   = (const float*)d_in[3];
    // d_in[4], d_in[5]: Wr, br — dead code (H == 0 kills the reset gate)
    const float* Wh   = (const float*)d_in[6];
    const float* bh   = (const float*)d_in[7];
    const float* lzw  = (const float*)d_in[8];
    const float* lzb  = (const float*)d_in[9];
    // d_in[10], d_in[11]: lr_w, lr_b — unused
    const float* lhw  = (const float*)d_in[12];
    const float* lhb  = (const float*)d_in[13];
    const float* att  = (const float*)d_in[14];
    const float* outw = (const float*)d_in[15];
    const float* outb = (const float*)d_in[16];
    float* out = (float*)d_out;

    fused_kernel<<<NBLK, NTHR>>>(x, ei, Wz, bz, Wh, bh, lzw, lzb, lhw, lhb,
                                 att, outw, outb, out);
}

// round 7
// speedup vs baseline: 1.7845x; 1.0407x over previous
#include <cuda_runtime.h>
#include <math.h>

#define NN 20000
#define FF 8
#define PP 12
#define OO 32
#define EE 320000
#define FP 96           // F*P floats per node row
#define SLOTS 96        // max in-degree slots (Poisson(16); guarded)
#define NSM 148
#define NBPS 5
#define NBLK (NSM * NBPS)            // 740 blocks, all co-resident
#define NTHR 256
#define WPB (NTHR / 32)              // 8 warps per block
#define FULL 0xffffffffu

// ---- scratch (static device globals; no allocation allowed) ----
__device__ int      g_cnt[NN];            // in-degree (atomic counters)
__device__ int      g_col[NN * SLOTS];    // slotted adjacency: srcs per dst
__device__ float    g_dinv[NN];           // (in_deg + 1)^-1/2
__device__ float    g_cwz[FF * OO];       // fused Wz @ Lz^T
__device__ float    g_cwh[FF * OO];       // fused Wh @ Lh^T
__device__ float    g_cbz[OO];
__device__ float    g_cbh[OO];
__device__ float    g_probs[PP];
__device__ unsigned g_node_ctr;           // P3 dynamic work counter (reset in P2)
__device__ unsigned g_bar[3];             // monotonic barrier counters (never reset)

// Monotonic grid barrier: all NBLK blocks co-resident (5/SM via launch bounds).
__device__ __forceinline__ void grid_barrier(int id) {
    __syncthreads();
    if (threadIdx.x == 0) {
        __threadfence();                                      // release
        unsigned arrived = atomicAdd(&g_bar[id], 1u) + 1u;
        unsigned target  = ((arrived + NBLK - 1u) / NBLK) * NBLK;
        while (*(volatile unsigned*)&g_bar[id] < target) { }
        __threadfence();                                      // acquire
    }
    __syncthreads();
}

// Packed fp32x2 helpers (Blackwell FFMA2 — only reachable via PTX)
__device__ __forceinline__ unsigned long long pack2(float lo, float hi) {
    unsigned long long r;
    asm("mov.b64 %0, {%1, %2};" : "=l"(r) : "f"(lo), "f"(hi));
    return r;
}
__device__ __forceinline__ void unpack2(unsigned long long v, float& lo, float& hi) {
    asm("mov.b64 {%0, %1}, %2;" : "=f"(lo), "=f"(hi) : "l"(v));
}
__device__ __forceinline__ unsigned long long ffma2(
        unsigned long long a, unsigned long long b, unsigned long long c) {
    unsigned long long d;
    asm("fma.rn.f32x2 %0, %1, %2, %3;" : "=l"(d) : "l"(a), "l"(b), "l"(c));
    return d;
}

__global__ void __launch_bounds__(NTHR, NBPS) fused_kernel(
        const float* __restrict__ x,
        const int*   __restrict__ ei,
        const float* __restrict__ Wz,  const float* __restrict__ bz,
        const float* __restrict__ Wh,  const float* __restrict__ bh,
        const float* __restrict__ lzw, const float* __restrict__ lzb,
        const float* __restrict__ lhw, const float* __restrict__ lhb,
        const float* __restrict__ att,
        const float* __restrict__ out_w, const float* __restrict__ out_b,
        float* __restrict__ out) {
    const int t    = threadIdx.x;
    const int lane = t & 31;
    const int warp = t >> 5;                 // 0..7
    const int gid  = blockIdx.x * NTHR + t;
    const int T    = NBLK * NTHR;

    __shared__ float buf[WPB][FP];           // GRU staging, per warp
    __shared__ float sow[PP * OO];           // staged out_w
    __shared__ float sob[PP];                // staged out_b
    __shared__ float sprobs[PP];             // staged softmax(att)

    // ---------------- P0: zero counters + fold weights (blocks 0..2) -------
    for (int j = gid; j < NN; j += T) g_cnt[j] = 0;

    if (blockIdx.x == 0) {                   // W'_z[f][o] = sum_k Wz[f][k]*lzw[o][k]
        int f = t >> 5, o = t & 31;
        float s = 0.f;
        #pragma unroll
        for (int k = 0; k < 32; ++k) s = fmaf(Wz[f * 32 + k], lzw[o * 64 + k], s);
        g_cwz[t] = s;
    } else if (blockIdx.x == 1) {            // W'_h
        int f = t >> 5, o = t & 31;
        float s = 0.f;
        #pragma unroll
        for (int k = 0; k < 32; ++k) s = fmaf(Wh[f * 32 + k], lhw[o * 64 + k], s);
        g_cwh[t] = s;
    } else if (blockIdx.x == 2) {
        if (t < 32) {                        // b'_z
            float s = lzb[t];
            #pragma unroll
            for (int k = 0; k < 32; ++k) s = fmaf(bz[k], lzw[t * 64 + k], s);
            g_cbz[t] = s;
        } else if (t < 64) {                 // b'_h
            int o = t - 32;
            float s = lhb[o];
            #pragma unroll
            for (int k = 0; k < 32; ++k) s = fmaf(bh[k], lhw[o * 64 + k], s);
            g_cbh[o] = s;
        } else if (t == 64) {                // softmax over 12 logits
            float m = att[0];
            for (int p = 1; p < PP; ++p) m = fmaxf(m, att[p]);
            float e[PP], sum = 0.f;
            for (int p = 0; p < PP; ++p) { e[p] = __expf(att[p] - m); sum += e[p]; }
            float inv = 1.f / sum;
            for (int p = 0; p < PP; ++p) g_probs[p] = e[p] * inv;
        }
    }
    grid_barrier(0);

    // ---------------- P1: single-pass slotted scatter -----------------------
    {
        const int4* s4p = (const int4*)ei;
        const int4* d4p = (const int4*)(ei + EE);
        for (int q = gid; q < EE / 4; q += T) {
            int4 s4 = s4p[q];
            int4 d4 = d4p[q];
            int p0 = atomicAdd(&g_cnt[d4.x], 1);
            int p1 = atomicAdd(&g_cnt[d4.y], 1);
            int p2 = atomicAdd(&g_cnt[d4.z], 1);
            int p3 = atomicAdd(&g_cnt[d4.w], 1);
            if (p0 < SLOTS) g_col[d4.x * SLOTS + p0] = s4.x;
            if (p1 < SLOTS) g_col[d4.y * SLOTS + p1] = s4.y;
            if (p2 < SLOTS) g_col[d4.z * SLOTS + p2] = s4.z;
            if (p3 < SLOTS) g_col[d4.w * SLOTS + p3] = s4.w;
        }
    }
    grid_barrier(1);

    // ---------------- P2: dinv + reset node counter ------------------------
    for (int j = gid; j < NN; j += T)
        g_dinv[j] = rsqrtf((float)(__ldcg(&g_cnt[j]) + 1));
    if (gid == 0) g_node_ctr = 0;
    grid_barrier(2);

    // ---------------- P3: gather + GRU + attention + readout ---------------
    {
        // stage small constants into smem
        if (t < PP) sprobs[t] = g_probs[t];
        if (t < PP) sob[t]    = out_b[t];
        for (int j = t; j < PP * OO; j += NTHR) sow[j] = out_w[j];
        __syncthreads();

        float wz[FF], wh[FF];
        #pragma unroll
        for (int f = 0; f < FF; ++f) {
            wz[f] = g_cwz[f * OO + lane];
            wh[f] = g_cwh[f * OO + lane];
        }
        const float bz_ = g_cbz[lane];
        const float bh_ = g_cbh[lane];

        for (;;) {
            // -------- dynamic work: warp pops a chunk of 2 nodes ----------
            int base;
            if (lane == 0) base = (int)atomicAdd(&g_node_ctr, 2u);
            base = __shfl_sync(FULL, base, 0);
            if (base >= NN) break;
            int nend = base + 2 < NN ? base + 2 : NN;

            for (int node = base; node < nend; ++node) {
                int deg = g_cnt[node];
                if (deg > SLOTS) deg = SLOTS;
                const int* cols = g_col + node * SLOTS;
                float di = g_dinv[node];

                float4 acc = make_float4(0.f, 0.f, 0.f, 0.f);

                // batches of up to 32 edges; srcs+weights lane-parallel
                for (int b = 0; b < deg; b += 32) {
                    int nb = deg - b; if (nb > 32) nb = 32;
                    int   cidx = (lane < nb) ? __ldg(&cols[b + lane]) : 0;
                    float wl   = (lane < nb) ? __ldg(&g_dinv[cidx])   : 0.f;

                    int k = 0;
                    for (; k + 2 <= nb; k += 2) {
                        int   s0 = __shfl_sync(FULL, cidx, k);
                        int   s1 = __shfl_sync(FULL, cidx, k + 1);
                        float w0 = __shfl_sync(FULL, wl,   k);
                        float w1 = __shfl_sync(FULL, wl,   k + 1);
                        if (lane < 24) {
                            float4 v0 = __ldg((const float4*)(x + (size_t)s0 * FP) + lane);
                            float4 v1 = __ldg((const float4*)(x + (size_t)s1 * FP) + lane);
                            acc.x = fmaf(w0, v0.x, acc.x); acc.y = fmaf(w0, v0.y, acc.y);
                            acc.z = fmaf(w0, v0.z, acc.z); acc.w = fmaf(w0, v0.w, acc.w);
                            acc.x = fmaf(w1, v1.x, acc.x); acc.y = fmaf(w1, v1.y, acc.y);
                            acc.z = fmaf(w1, v1.z, acc.z); acc.w = fmaf(w1, v1.w, acc.w);
                        }
                    }
                    if (k < nb) {
                        int   s0 = __shfl_sync(FULL, cidx, k);
                        float w0 = __shfl_sync(FULL, wl,   k);
                        if (lane < 24) {
                            float4 v0 = __ldg((const float4*)(x + (size_t)s0 * FP) + lane);
                            acc.x = fmaf(w0, v0.x, acc.x); acc.y = fmaf(w0, v0.y, acc.y);
                            acc.z = fmaf(w0, v0.z, acc.z); acc.w = fmaf(w0, v0.w, acc.w);
                        }
                    }
                }

                // agg = di * (acc + di * x_self); stage to smem
                if (lane < 24) {
                    float4 xv = __ldg((const float4*)(x + (size_t)node * FP) + lane);
                    acc.x = di * fmaf(di, xv.x, acc.x);
                    acc.y = di * fmaf(di, xv.y, acc.y);
                    acc.z = di * fmaf(di, xv.z, acc.z);
                    acc.w = di * fmaf(di, xv.w, acc.w);
                    ((float4*)buf[warp])[lane] = acc;
                }
                __syncwarp();

                // ---- GRU: packed f32x2 over period pairs, f-outer ----------
                unsigned long long zp[PP / 2], hp[PP / 2];
                {
                    unsigned long long bz2 = pack2(bz_, bz_);
                    unsigned long long bh2 = pack2(bh_, bh_);
                    #pragma unroll
                    for (int q = 0; q < PP / 2; ++q) { zp[q] = bz2; hp[q] = bh2; }
                }
                #pragma unroll
                for (int f = 0; f < FF; ++f) {
                    unsigned long long wz2 = pack2(wz[f], wz[f]);
                    unsigned long long wh2 = pack2(wh[f], wh[f]);
                    #pragma unroll
                    for (int q = 0; q < PP / 2; ++q) {
                        unsigned long long v2 =
                            *(const unsigned long long*)&buf[warp][f * PP + 2 * q];
                        zp[q] = ffma2(v2, wz2, zp[q]);
                        hp[q] = ffma2(v2, wh2, hp[q]);
                    }
                }
                float hacc = 0.f;
                #pragma unroll
                for (int q = 0; q < PP / 2; ++q) {
                    float z0, z1, h0, h1;
                    unpack2(zp[q], z0, z1);
                    unpack2(hp[q], h0, h1);
                    float Z0 = 1.f / (1.f + __expf(-z0));
                    float Z1 = 1.f / (1.f + __expf(-z1));
                    float T0 = 2.f / (1.f + __expf(-2.f * h0)) - 1.f;
                    float T1 = 2.f / (1.f + __expf(-2.f * h1)) - 1.f;
                    hacc = fmaf(sprobs[2 * q],     (1.f - Z0) * T0, hacc);
                    hacc = fmaf(sprobs[2 * q + 1], (1.f - Z1) * T1, hacc);
                }
                float hr = fmaxf(hacc, 0.f);     // relu
                __syncwarp();                    // buf reads done before next node

                // ---- readout ------------------------------------------------
                float myout = 0.f;
                #pragma unroll
                for (int p = 0; p < PP; ++p) {
                    float v = hr * sow[p * OO + lane];
                    v += __shfl_xor_sync(FULL, v, 16);
                    v += __shfl_xor_sync(FULL, v, 8);
                    v += __shfl_xor_sync(FULL, v, 4);
                    v += __shfl_xor_sync(FULL, v, 2);
                    v += __shfl_xor_sync(FULL, v, 1);
                    if (lane == p) myout = v + sob[p];
                }
                if (lane < PP) out[node * PP + lane] = myout;
            }
        }
    }
}

// ---------------------------------------------------------------------------
extern "C" void kernel_launch(void* const* d_in, const int* in_sizes, int n_in,
                              void* d_out, int out_size) {
    const float* x    = (const float*)d_in[0];
    const int*   ei   = (const int*)  d_in[1];
    const float* Wz   = (const float*)d_in[2];
    const float* bz   = (const float*)d_in[3];
    // d_in[4], d_in[5]: Wr, br — dead code (H == 0 kills the reset gate)
    const float* Wh   = (const float*)d_in[6];
    const float* bh   = (const float*)d_in[7];
    const float* lzw  = (const float*)d_in[8];
    const float* lzb  = (const float*)d_in[9];
    // d_in[10], d_in[11]: lr_w, lr_b — unused
    const float* lhw  = (const float*)d_in[12];
    const float* lhb  = (const float*)d_in[13];
    const float* att  = (const float*)d_in[14];
    const float* outw = (const float*)d_in[15];
    const float* outb = (const float*)d_in[16];
    float* out = (float*)d_out;

    fused_kernel<<<NBLK, NTHR>>>(x, ei, Wz, bz, Wh, bh, lzw, lzb, lhw, lhb,
                                 att, outw, outb, out);
}

// round 8
// speedup vs baseline: 2.2763x; 1.2756x over previous
#include <cuda_runtime.h>
#include <math.h>

#define NN 20000
#define FF 8
#define PP 12
#define OO 32
#define EE 320000
#define FP 96           // F*P floats per node row
#define SLOTS 96        // max in-degree slots (Poisson(16); guarded)
#define NSM 148
#define NBPS 4
#define NBLK (NSM * NBPS)            // 592 blocks, all co-resident
#define NTHR 256
#define WPB (NTHR / 32)              // 8 warps per block
#define FULL 0xffffffffu

// ---- scratch (static device globals; no allocation allowed) ----
__device__ int      g_cnt[NN];            // in-degree (atomic counters)
__device__ int      g_col[NN * SLOTS];    // slotted adjacency: srcs per dst
__device__ float    g_dinv[NN];           // (in_deg + 1)^-1/2
__device__ float    g_cwz[FF * OO];       // fused Wz @ Lz^T
__device__ float    g_cwh[FF * OO];       // fused Wh @ Lh^T
__device__ float    g_cbz[OO];
__device__ float    g_cbh[OO];
__device__ float    g_probs[PP];
__device__ unsigned g_node_ctr;           // P3 dynamic work counter (reset in P2)
__device__ unsigned g_bar[3];             // monotonic barrier counters (never reset)

// Monotonic grid barrier: all NBLK blocks co-resident (4/SM via launch bounds).
__device__ __forceinline__ void grid_barrier(int id) {
    __syncthreads();
    if (threadIdx.x == 0) {
        __threadfence();                                      // release
        unsigned arrived = atomicAdd(&g_bar[id], 1u) + 1u;
        unsigned target  = ((arrived + NBLK - 1u) / NBLK) * NBLK;
        while (*(volatile unsigned*)&g_bar[id] < target) { }
        __threadfence();                                      // acquire
    }
    __syncthreads();
}

// Packed fp32x2 helpers (Blackwell FFMA2 — only reachable via PTX)
__device__ __forceinline__ unsigned long long pack2(float lo, float hi) {
    unsigned long long r;
    asm("mov.b64 %0, {%1, %2};" : "=l"(r) : "f"(lo), "f"(hi));
    return r;
}
__device__ __forceinline__ void unpack2(unsigned long long v, float& lo, float& hi) {
    asm("mov.b64 {%0, %1}, %2;" : "=f"(lo), "=f"(hi) : "l"(v));
}
__device__ __forceinline__ unsigned long long ffma2(
        unsigned long long a, unsigned long long b, unsigned long long c) {
    unsigned long long d;
    asm("fma.rn.f32x2 %0, %1, %2, %3;" : "=l"(d) : "l"(a), "l"(b), "l"(c));
    return d;
}
// HW tanh (sm_75+ MUFU.TANH), rel err ~1e-5 — far inside the 1e-3 budget
__device__ __forceinline__ float htanh(float x) {
    float r;
    asm("tanh.approx.f32 %0, %1;" : "=f"(r) : "f"(x));
    return r;
}

__global__ void __launch_bounds__(NTHR, NBPS) fused_kernel(
        const float* __restrict__ x,
        const int*   __restrict__ ei,
        const float* __restrict__ Wz,  const float* __restrict__ bz,
        const float* __restrict__ Wh,  const float* __restrict__ bh,
        const float* __restrict__ lzw, const float* __restrict__ lzb,
        const float* __restrict__ lhw, const float* __restrict__ lhb,
        const float* __restrict__ att,
        const float* __restrict__ out_w, const float* __restrict__ out_b,
        float* __restrict__ out) {
    const int t    = threadIdx.x;
    const int lane = t & 31;
    const int warp = t >> 5;                 // 0..7
    const int gid  = blockIdx.x * NTHR + t;
    const int T    = NBLK * NTHR;

    __shared__ float buf[WPB][FP];           // GRU staging, per warp
    __shared__ float sow[PP * OO];           // staged out_w
    __shared__ float sob[PP];                // staged out_b
    __shared__ float sp2[PP];                // 0.5 * softmax(att)

    // ---------------- P0: zero counters + fold weights (blocks 0..2) -------
    for (int j = gid; j < NN; j += T) g_cnt[j] = 0;

    if (blockIdx.x == 0) {                   // W'_z[f][o] = sum_k Wz[f][k]*lzw[o][k]
        int f = t >> 5, o = t & 31;
        float s = 0.f;
        #pragma unroll
        for (int k = 0; k < 32; ++k) s = fmaf(Wz[f * 32 + k], lzw[o * 64 + k], s);
        g_cwz[t] = s;
    } else if (blockIdx.x == 1) {            // W'_h
        int f = t >> 5, o = t & 31;
        float s = 0.f;
        #pragma unroll
        for (int k = 0; k < 32; ++k) s = fmaf(Wh[f * 32 + k], lhw[o * 64 + k], s);
        g_cwh[t] = s;
    } else if (blockIdx.x == 2) {
        if (t < 32) {                        // b'_z
            float s = lzb[t];
            #pragma unroll
            for (int k = 0; k < 32; ++k) s = fmaf(bz[k], lzw[t * 64 + k], s);
            g_cbz[t] = s;
        } else if (t < 64) {                 // b'_h
            int o = t - 32;
            float s = lhb[o];
            #pragma unroll
            for (int k = 0; k < 32; ++k) s = fmaf(bh[k], lhw[o * 64 + k], s);
            g_cbh[o] = s;
        } else if (t == 64) {                // softmax over 12 logits
            float m = att[0];
            for (int p = 1; p < PP; ++p) m = fmaxf(m, att[p]);
            float e[PP], sum = 0.f;
            for (int p = 0; p < PP; ++p) { e[p] = __expf(att[p] - m); sum += e[p]; }
            float inv = 1.f / sum;
            for (int p = 0; p < PP; ++p) g_probs[p] = e[p] * inv;
        }
    }
    grid_barrier(0);

    // ---------------- P1: single-pass slotted scatter -----------------------
    {
        const int4* s4p = (const int4*)ei;
        const int4* d4p = (const int4*)(ei + EE);
        for (int q = gid; q < EE / 4; q += T) {
            int4 s4 = s4p[q];
            int4 d4 = d4p[q];
            int p0 = atomicAdd(&g_cnt[d4.x], 1);
            int p1 = atomicAdd(&g_cnt[d4.y], 1);
            int p2 = atomicAdd(&g_cnt[d4.z], 1);
            int p3 = atomicAdd(&g_cnt[d4.w], 1);
            if (p0 < SLOTS) g_col[d4.x * SLOTS + p0] = s4.x;
            if (p1 < SLOTS) g_col[d4.y * SLOTS + p1] = s4.y;
            if (p2 < SLOTS) g_col[d4.z * SLOTS + p2] = s4.z;
            if (p3 < SLOTS) g_col[d4.w * SLOTS + p3] = s4.w;
        }
    }
    grid_barrier(1);

    // ---------------- P2: dinv + reset node counter ------------------------
    for (int j = gid; j < NN; j += T)
        g_dinv[j] = rsqrtf((float)(__ldcg(&g_cnt[j]) + 1));
    if (gid == 0) g_node_ctr = 0;
    grid_barrier(2);

    // ---------------- P3: gather + GRU + attention + readout ---------------
    {
        if (t < PP) sp2[t] = 0.5f * g_probs[t];   // fold sigmoid's 0.5
        if (t < PP) sob[t] = out_b[t];
        for (int j = t; j < PP * OO; j += NTHR) sow[j] = out_w[j];
        __syncthreads();

        float wz[FF], wh[FF];
        #pragma unroll
        for (int f = 0; f < FF; ++f) {
            wz[f] = g_cwz[f * OO + lane];
            wh[f] = g_cwh[f * OO + lane];
        }
        const float bz_ = g_cbz[lane];
        const float bh_ = g_cbh[lane];

        for (;;) {
            int base;
            if (lane == 0) base = (int)atomicAdd(&g_node_ctr, 2u);
            base = __shfl_sync(FULL, base, 0);
            if (base >= NN) break;
            int nend = base + 2 < NN ? base + 2 : NN;

            for (int node = base; node < nend; ++node) {
                int deg = g_cnt[node];
                if (deg > SLOTS) deg = SLOTS;
                const int* cols = g_col + node * SLOTS;
                float di = g_dinv[node];

                float4 acc = make_float4(0.f, 0.f, 0.f, 0.f);

                // batches of up to 32 edges; srcs+weights lane-parallel.
                // inner groups of 4 edges: 4 independent LDG.128 in flight
                // before any consuming FMA (deg padded via zero weights).
                for (int b = 0; b < deg; b += 32) {
                    int nb = deg - b; if (nb > 32) nb = 32;
                    int   cidx = (lane < nb) ? __ldg(&cols[b + lane]) : 0;
                    float wl   = (lane < nb) ? __ldg(&g_dinv[cidx])   : 0.f;
                    int nb4 = (nb + 3) & ~3;

                    for (int k = 0; k < nb4; k += 4) {
                        int   s0 = __shfl_sync(FULL, cidx, k);
                        int   s1 = __shfl_sync(FULL, cidx, k + 1);
                        int   s2 = __shfl_sync(FULL, cidx, k + 2);
                        int   s3 = __shfl_sync(FULL, cidx, k + 3);
                        float w0 = __shfl_sync(FULL, wl, k);
                        float w1 = __shfl_sync(FULL, wl, k + 1);
                        float w2 = __shfl_sync(FULL, wl, k + 2);
                        float w3 = __shfl_sync(FULL, wl, k + 3);
                        if (lane < 24) {
                            float4 v0 = __ldg((const float4*)(x + (size_t)s0 * FP) + lane);
                            float4 v1 = __ldg((const float4*)(x + (size_t)s1 * FP) + lane);
                            float4 v2 = __ldg((const float4*)(x + (size_t)s2 * FP) + lane);
                            float4 v3 = __ldg((const float4*)(x + (size_t)s3 * FP) + lane);
                            acc.x = fmaf(w0, v0.x, acc.x); acc.y = fmaf(w0, v0.y, acc.y);
                            acc.z = fmaf(w0, v0.z, acc.z); acc.w = fmaf(w0, v0.w, acc.w);
                            acc.x = fmaf(w1, v1.x, acc.x); acc.y = fmaf(w1, v1.y, acc.y);
                            acc.z = fmaf(w1, v1.z, acc.z); acc.w = fmaf(w1, v1.w, acc.w);
                            acc.x = fmaf(w2, v2.x, acc.x); acc.y = fmaf(w2, v2.y, acc.y);
                            acc.z = fmaf(w2, v2.z, acc.z); acc.w = fmaf(w2, v2.w, acc.w);
                            acc.x = fmaf(w3, v3.x, acc.x); acc.y = fmaf(w3, v3.y, acc.y);
                            acc.z = fmaf(w3, v3.z, acc.z); acc.w = fmaf(w3, v3.w, acc.w);
                        }
                    }
                }

                // agg = di * (acc + di * x_self); stage to smem
                if (lane < 24) {
                    float4 xv = __ldg((const float4*)(x + (size_t)node * FP) + lane);
                    acc.x = di * fmaf(di, xv.x, acc.x);
                    acc.y = di * fmaf(di, xv.y, acc.y);
                    acc.z = di * fmaf(di, xv.z, acc.z);
                    acc.w = di * fmaf(di, xv.w, acc.w);
                    ((float4*)buf[warp])[lane] = acc;
                }
                __syncwarp();

                // ---- GRU: packed f32x2 over period pairs, f-outer ----------
                unsigned long long zp[PP / 2], hp[PP / 2];
                {
                    unsigned long long bz2 = pack2(bz_, bz_);
                    unsigned long long bh2 = pack2(bh_, bh_);
                    #pragma unroll
                    for (int q = 0; q < PP / 2; ++q) { zp[q] = bz2; hp[q] = bh2; }
                }
                #pragma unroll
                for (int f = 0; f < FF; ++f) {
                    unsigned long long wz2 = pack2(wz[f], wz[f]);
                    unsigned long long wh2 = pack2(wh[f], wh[f]);
                    #pragma unroll
                    for (int q = 0; q < PP / 2; ++q) {
                        unsigned long long v2 =
                            *(const unsigned long long*)&buf[warp][f * PP + 2 * q];
                        zp[q] = ffma2(v2, wz2, zp[q]);
                        hp[q] = ffma2(v2, wh2, hp[q]);
                    }
                }
                // contribution: probs*(1-Z)*tanh(h), Z = 0.5 + 0.5*tanh(z/2)
                //   => (0.5*probs) * (1 - tanh(z/2)) * tanh(h)
                float hacc = 0.f;
                #pragma unroll
                for (int q = 0; q < PP / 2; ++q) {
                    float z0, z1, h0, h1;
                    unpack2(zp[q], z0, z1);
                    unpack2(hp[q], h0, h1);
                    float tz0 = htanh(0.5f * z0);
                    float tz1 = htanh(0.5f * z1);
                    float th0 = htanh(h0);
                    float th1 = htanh(h1);
                    hacc = fmaf(sp2[2 * q],     (1.f - tz0) * th0, hacc);
                    hacc = fmaf(sp2[2 * q + 1], (1.f - tz1) * th1, hacc);
                }
                float hr = fmaxf(hacc, 0.f);     // relu
                __syncwarp();                    // buf reads done before next node

                // ---- readout ------------------------------------------------
                float myout = 0.f;
                #pragma unroll
                for (int p = 0; p < PP; ++p) {
                    float v = hr * sow[p * OO + lane];
                    v += __shfl_xor_sync(FULL, v, 16);
                    v += __shfl_xor_sync(FULL, v, 8);
                    v += __shfl_xor_sync(FULL, v, 4);
                    v += __shfl_xor_sync(FULL, v, 2);
                    v += __shfl_xor_sync(FULL, v, 1);
                    if (lane == p) myout = v + sob[p];
                }
                if (lane < PP) out[node * PP + lane] = myout;
            }
        }
    }
}

// ---------------------------------------------------------------------------
extern "C" void kernel_launch(void* const* d_in, const int* in_sizes, int n_in,
                              void* d_out, int out_size) {
    const float* x    = (const float*)d_in[0];
    const int*   ei   = (const int*)  d_in[1];
    const float* Wz   = (const float*)d_in[2];
    const float* bz   = (const float*)d_in[3];
    // d_in[4], d_in[5]: Wr, br — dead code (H == 0 kills the reset gate)
    const float* Wh   = (const float*)d_in[6];
    const float* bh   = (const float*)d_in[7];
    const float* lzw  = (const float*)d_in[8];
    const float* lzb  = (const float*)d_in[9];
    // d_in[10], d_in[11]: lr_w, lr_b — unused
    const float* lhw  = (const float*)d_in[12];
    const float* lhb  = (const float*)d_in[13];
    const float* att  = (const float*)d_in[14];
    const float* outw = (const float*)d_in[15];
    const float* outb = (const float*)d_in[16];
    float* out = (float*)d_out;

    fused_kernel<<<NBLK, NTHR>>>(x, ei, Wz, bz, Wh, bh, lzw, lzb, lhw, lhb,
                                 att, outw, outb, out);
}